// round 1
// baseline (speedup 1.0000x reference)
#include <cuda_runtime.h>
#include <math.h>

#define TPB 256

namespace {

constexpr int B_ = 4, N_ = 1024, D_ = 512, H_ = 8, DH_ = 64, BH_ = 32, KHOP = 3;

// Device-global scratch (no allocations allowed)
__device__ float g_S [(size_t)BH_ * N_ * N_];   // 128 MB: scores -> adjacency (in place)
__device__ float g_P0[(size_t)BH_ * N_ * DH_];  // 8 MB
__device__ float g_P1[(size_t)BH_ * N_ * DH_];  // 8 MB
__device__ float g_H [(size_t)B_ * N_ * D_];    // 8 MB: filtered output, head-concat layout

// ---------------------------------------------------------------------------
// Shared-tile loader: 64x64 float block, row stride ldg (floats).
// Stored as float4 groups with XOR swizzle: phys_group = k4 ^ (row>>2).
// Global loads fully coalesced; STS.128 conflict-free; all reads conflict-free.
// ---------------------------------------------------------------------------
__device__ __forceinline__ void load_tile(float4* s, const float* g, int ldg) {
    int t = threadIdx.x;
#pragma unroll
    for (int i = 0; i < 4; i++) {
        int idx = t + i * TPB;          // 0..1023
        int r  = idx >> 4;              // row 0..63
        int k4 = idx & 15;              // float4 group 0..15
        s[r * 16 + (k4 ^ (r >> 2))] =
            *(const float4*)(g + (size_t)r * ldg + (k4 << 2));
    }
}

__device__ __forceinline__ float getc(const float4& v, int c) {
    return c == 0 ? v.x : c == 1 ? v.y : c == 2 ? v.z : v.w;
}

// ---------------------------------------------------------------------------
// Pack Xh: P0[bh][n][d] = X[b][n][h*64+d]
// ---------------------------------------------------------------------------
__global__ __launch_bounds__(TPB) void pack_kernel(const float* __restrict__ X) {
    int idx = blockIdx.x * TPB + threadIdx.x;        // 0..524287 float4s
    int d4 = idx & 15;
    int n  = (idx >> 4) & (N_ - 1);
    int bh = idx >> 14;
    int b = bh >> 3, h = bh & 7;
    float4 v = *(const float4*)(X + ((size_t)b * N_ + n) * D_ + h * DH_ + (d4 << 2));
    *(float4*)(g_P0 + ((size_t)bh * N_ + n) * DH_ + (d4 << 2)) = v;
}

// ---------------------------------------------------------------------------
// Scores: S[bh][i][j] = <Xh_i, Xh_j> / (8 * clip(tau_h)).  64x64 tile, K=64.
// Variant-1 microkernel (both operands K-contiguous): C = A * B^T
// ---------------------------------------------------------------------------
__global__ __launch_bounds__(TPB) void score_kernel(const float* __restrict__ X,
                                                    const float* __restrict__ temp) {
    __shared__ float4 As[64 * 16], Bs[64 * 16];
    int bh = blockIdx.z, b = bh >> 3, h = bh & 7;
    const float* Xb = X + (size_t)b * N_ * D_ + h * DH_;
    int it = blockIdx.y << 6, jt = blockIdx.x << 6;

    load_tile(As, Xb + (size_t)it * D_, D_);
    load_tile(Bs, Xb + (size_t)jt * D_, D_);
    __syncthreads();

    int tx = threadIdx.x & 15, ty = threadIdx.x >> 4;
    float acc[4][4] = {};
#pragma unroll
    for (int k4 = 0; k4 < 16; k4++) {
        float4 a[4], bb[4];
#pragma unroll
        for (int i = 0; i < 4; i++) a[i]  = As[(ty * 4 + i) * 16 + (k4 ^ ty)];
#pragma unroll
        for (int j = 0; j < 4; j++) bb[j] = Bs[(tx * 4 + j) * 16 + (k4 ^ tx)];
#pragma unroll
        for (int i = 0; i < 4; i++)
#pragma unroll
            for (int j = 0; j < 4; j++)
                acc[i][j] += a[i].x * bb[j].x + a[i].y * bb[j].y +
                             a[i].z * bb[j].z + a[i].w * bb[j].w;
    }

    float tau = fminf(fmaxf(temp[h], 0.1f), 5.0f);
    float sc = 1.0f / (8.0f * tau);
    float* Srow = g_S + (size_t)bh * N_ * N_;
#pragma unroll
    for (int i = 0; i < 4; i++) {
        float4 o = make_float4(acc[i][0] * sc, acc[i][1] * sc,
                               acc[i][2] * sc, acc[i][3] * sc);
        *(float4*)(Srow + (size_t)(it + ty * 4 + i) * N_ + jt + tx * 4) = o;
    }
}

// ---------------------------------------------------------------------------
// Exact top-k threshold + softmax, warp-per-row.
// Bitwise binary search on order-preserving uint keys -> exact k-th largest
// value (matches jax top_k + (S < thresh -> -inf) tie semantics exactly).
// ---------------------------------------------------------------------------
__global__ __launch_bounds__(TPB) void topk_softmax_kernel(const int* __restrict__ layer_idx,
                                                           const int* __restrict__ Lp) {
    int lane = threadIdx.x & 31;
    int gw = blockIdx.x * (TPB / 32) + (threadIdx.x >> 5);  // row id 0..32767
    float* srow = g_S + (size_t)gw * N_;

    unsigned uu[32];
#pragma unroll
    for (int i = 0; i < 32; i++) {
        unsigned bits = __float_as_uint(srow[lane + i * 32]);
        uu[i] = (bits & 0x80000000u) ? ~bits : (bits | 0x80000000u);
    }

    int li = layer_idx[0], Lv = Lp[0];
    double sp = 0.8 + (0.2 - 0.8) * exp(-3.0 * (double)li / (double)Lv);
    int k_val = (int)((1.0 - sp) * (double)N_);
    if (k_val < 1) k_val = 1;
    bool do_thresh = (k_val < N_);

    unsigned T = 0u;
    if (do_thresh) {
#pragma unroll 1
        for (int b = 31; b >= 0; --b) {
            unsigned cand = T | (1u << b);
            int c = 0;
#pragma unroll
            for (int i = 0; i < 32; i++) c += (uu[i] >= cand) ? 1 : 0;
            c = __reduce_add_sync(0xFFFFFFFFu, c);
            if (c >= k_val) T = cand;
        }
    }

    // Reconstruct values; row max (max element always survives the threshold).
    float v[32];
    float vmax = -INFINITY;
#pragma unroll
    for (int i = 0; i < 32; i++) {
        unsigned u = uu[i];
        unsigned bits = (u & 0x80000000u) ? (u ^ 0x80000000u) : ~u;
        v[i] = __uint_as_float(bits);
        vmax = fmaxf(vmax, v[i]);
    }
#pragma unroll
    for (int o = 16; o > 0; o >>= 1)
        vmax = fmaxf(vmax, __shfl_xor_sync(0xFFFFFFFFu, vmax, o));

    float ssum = 0.f;
#pragma unroll
    for (int i = 0; i < 32; i++) {
        bool keep = (!do_thresh) || (uu[i] >= T);
        float ev = keep ? expf(v[i] - vmax) : 0.f;
        v[i] = ev;              // reuse registers
        ssum += ev;
    }
#pragma unroll
    for (int o = 16; o > 0; o >>= 1)
        ssum += __shfl_xor_sync(0xFFFFFFFFu, ssum, o);
    float inv = 1.0f / ssum;

#pragma unroll
    for (int i = 0; i < 32; i++) srow[lane + i * 32] = v[i] * inv;
}

// ---------------------------------------------------------------------------
// Hop propagation: Pout = A @ Pin  per (b,h).  M=1024,K=1024,N=64.
// Variant-2 microkernel (B is k-major).
// ---------------------------------------------------------------------------
__global__ __launch_bounds__(TPB) void spmm_kernel(int in_sel) {
    __shared__ float4 As[64 * 16], Bs[64 * 16];
    int bh = blockIdx.y;
    const float* A    = g_S + (size_t)bh * N_ * N_;
    const float* Pin  = (in_sel ? g_P1 : g_P0) + (size_t)bh * N_ * DH_;
    float*       Pout = (in_sel ? g_P0 : g_P1) + (size_t)bh * N_ * DH_;
    int mt = blockIdx.x << 6;
    int tx = threadIdx.x & 15, ty = threadIdx.x >> 4;

    float4 acc[4];
    acc[0] = acc[1] = acc[2] = acc[3] = make_float4(0.f, 0.f, 0.f, 0.f);

    for (int kc = 0; kc < 16; kc++) {
        load_tile(As, A + (size_t)mt * N_ + kc * 64, N_);
        load_tile(Bs, Pin + (size_t)(kc * 64) * DH_, DH_);
        __syncthreads();
#pragma unroll
        for (int k4 = 0; k4 < 16; k4++) {
            float4 a[4];
#pragma unroll
            for (int i = 0; i < 4; i++) a[i] = As[(ty * 4 + i) * 16 + (k4 ^ ty)];
#pragma unroll
            for (int c = 0; c < 4; c++) {
                float4 bv = Bs[(k4 * 4 + c) * 16 + (tx ^ k4)];
#pragma unroll
                for (int i = 0; i < 4; i++) {
                    float s = getc(a[i], c);
                    acc[i].x += s * bv.x; acc[i].y += s * bv.y;
                    acc[i].z += s * bv.z; acc[i].w += s * bv.w;
                }
            }
        }
        __syncthreads();
    }
#pragma unroll
    for (int i = 0; i < 4; i++)
        *(float4*)(Pout + (size_t)(mt + ty * 4 + i) * DH_ + tx * 4) = acc[i];
}

// ---------------------------------------------------------------------------
// Filter: H[b, n, h*64+e] (+)= alpha[h,hop] * sum_d P[bh][n][d] * W[h,hop][d][e]
// ---------------------------------------------------------------------------
__global__ __launch_bounds__(TPB) void filter_kernel(const float* __restrict__ Wf,
                                                     const float* __restrict__ alpha,
                                                     int hop) {
    __shared__ float4 As[64 * 16], Bs[64 * 16];
    int bh = blockIdx.y, b = bh >> 3, h = bh & 7;
    const float* Pin = ((hop & 1) ? g_P1 : g_P0) + (size_t)bh * N_ * DH_;
    const float* W   = Wf + (size_t)(h * (KHOP + 1) + hop) * DH_ * DH_;
    int mt = blockIdx.x << 6;
    int tx = threadIdx.x & 15, ty = threadIdx.x >> 4;

    load_tile(As, Pin + (size_t)mt * DH_, DH_);
    load_tile(Bs, W, DH_);
    __syncthreads();

    float4 acc[4];
    acc[0] = acc[1] = acc[2] = acc[3] = make_float4(0.f, 0.f, 0.f, 0.f);
#pragma unroll
    for (int k4 = 0; k4 < 16; k4++) {
        float4 a[4];
#pragma unroll
        for (int i = 0; i < 4; i++) a[i] = As[(ty * 4 + i) * 16 + (k4 ^ ty)];
#pragma unroll
        for (int c = 0; c < 4; c++) {
            float4 bv = Bs[(k4 * 4 + c) * 16 + (tx ^ k4)];
#pragma unroll
            for (int i = 0; i < 4; i++) {
                float s = getc(a[i], c);
                acc[i].x += s * bv.x; acc[i].y += s * bv.y;
                acc[i].z += s * bv.z; acc[i].w += s * bv.w;
            }
        }
    }

    float av = alpha[h * (KHOP + 1) + hop];
    float* Hb = g_H + ((size_t)(b * N_ + mt)) * D_ + h * DH_;
#pragma unroll
    for (int i = 0; i < 4; i++) {
        float4 o = make_float4(acc[i].x * av, acc[i].y * av,
                               acc[i].z * av, acc[i].w * av);
        float4* dst = (float4*)(Hb + (size_t)(ty * 4 + i) * D_ + tx * 4);
        if (hop == 0) {
            *dst = o;
        } else {
            float4 p = *dst;
            p.x += o.x; p.y += o.y; p.z += o.z; p.w += o.w;
            *dst = p;
        }
    }
}

// ---------------------------------------------------------------------------
// Projection: out[i][j] = sum_d H[i][d] * W_proj[j][d] + b_proj[j]
// M=4096, N=512, K=512.  Variant-1 microkernel.
// ---------------------------------------------------------------------------
__global__ __launch_bounds__(TPB) void proj_kernel(const float* __restrict__ Wp,
                                                   const float* __restrict__ bias,
                                                   float* __restrict__ out) {
    __shared__ float4 As[64 * 16], Bs[64 * 16];
    int it = blockIdx.y << 6;   // row tile (0..4095)
    int jt = blockIdx.x << 6;   // col tile (0..511)
    int tx = threadIdx.x & 15, ty = threadIdx.x >> 4;
    float acc[4][4] = {};

    for (int kc = 0; kc < 8; kc++) {
        load_tile(As, g_H + (size_t)it * D_ + kc * 64, D_);
        load_tile(Bs, Wp + (size_t)jt * D_ + kc * 64, D_);
        __syncthreads();
#pragma unroll
        for (int k4 = 0; k4 < 16; k4++) {
            float4 a[4], bb[4];
#pragma unroll
            for (int i = 0; i < 4; i++) a[i]  = As[(ty * 4 + i) * 16 + (k4 ^ ty)];
#pragma unroll
            for (int j = 0; j < 4; j++) bb[j] = Bs[(tx * 4 + j) * 16 + (k4 ^ tx)];
#pragma unroll
            for (int i = 0; i < 4; i++)
#pragma unroll
                for (int j = 0; j < 4; j++)
                    acc[i][j] += a[i].x * bb[j].x + a[i].y * bb[j].y +
                                 a[i].z * bb[j].z + a[i].w * bb[j].w;
        }
        __syncthreads();
    }

    float4 bb4 = *(const float4*)(bias + jt + tx * 4);
#pragma unroll
    for (int i = 0; i < 4; i++) {
        float4 o = make_float4(acc[i][0] + bb4.x, acc[i][1] + bb4.y,
                               acc[i][2] + bb4.z, acc[i][3] + bb4.w);
        *(float4*)(out + (size_t)(it + ty * 4 + i) * D_ + jt + tx * 4) = o;
    }
}

}  // namespace

extern "C" void kernel_launch(void* const* d_in, const int* in_sizes, int n_in,
                              void* d_out, int out_size) {
    const float* X           = (const float*)d_in[0];
    const float* temperature = (const float*)d_in[1];
    const float* W_filt      = (const float*)d_in[2];
    const float* alpha       = (const float*)d_in[3];
    const float* W_proj      = (const float*)d_in[4];
    const float* b_proj      = (const float*)d_in[5];
    const int*   layer_idx   = (const int*)d_in[6];
    const int*   Lp          = (const int*)d_in[7];
    float* out = (float*)d_out;
    (void)in_sizes; (void)n_in; (void)out_size;

    // 1) Pack Xh -> P0
    pack_kernel<<<2048, TPB>>>(X);
    // 2) Per-head scaled scores S (overwritten to adjacency A in step 3)
    score_kernel<<<dim3(16, 16, 32), TPB>>>(X, temperature);
    // 3) Exact top-k threshold + row softmax (in-place on g_S)
    topk_softmax_kernel<<<4096, TPB>>>(layer_idx, Lp);
    // 4) Hop 0 filter contribution (initializes H)
    filter_kernel<<<dim3(16, 32), TPB>>>(W_filt, alpha, 0);
    // 5) Hops 1..3: propagate then accumulate filter
    for (int k = 1; k <= KHOP; k++) {
        spmm_kernel<<<dim3(16, 32), TPB>>>((k - 1) & 1);
        filter_kernel<<<dim3(16, 32), TPB>>>(W_filt, alpha, k);
    }
    // 6) Output projection + bias
    proj_kernel<<<dim3(8, 64), TPB>>>(W_proj, b_proj, out);
}

// round 2
// speedup vs baseline: 1.0872x; 1.0872x over previous
#include <cuda_runtime.h>
#include <math.h>

#define TPB 256

namespace {

constexpr int B_ = 4, N_ = 1024, D_ = 512, H_ = 8, DH_ = 64, BH_ = 32, KHOP = 3;

using u64 = unsigned long long;

// Device-global scratch (no allocations allowed)
__device__ float g_S [(size_t)BH_ * N_ * N_];   // 128 MB: scores -> adjacency (in place)
__device__ float g_P0[(size_t)BH_ * N_ * DH_];  // 8 MB
__device__ float g_P1[(size_t)BH_ * N_ * DH_];  // 8 MB
__device__ float g_H [(size_t)B_ * N_ * D_];    // 8 MB: filtered output, head-concat layout

// ---------------------------------------------------------------------------
// Packed f32x2 helpers (FFMA2: 2 fp32 FMAs per instruction, PTX-only path)
// ---------------------------------------------------------------------------
__device__ __forceinline__ u64 ffma2(u64 a, u64 b, u64 c) {
    u64 d;
    asm("fma.rn.f32x2 %0, %1, %2, %3;" : "=l"(d) : "l"(a), "l"(b), "l"(c));
    return d;
}
__device__ __forceinline__ u64 dup2(float s) {
    u64 d;
    asm("mov.b64 %0, {%1, %1};" : "=l"(d) : "f"(s));
    return d;
}
__device__ __forceinline__ float2 unpack2(u64 v) {
    float2 r;
    asm("mov.b64 {%0, %1}, %2;" : "=f"(r.x), "=f"(r.y) : "l"(v));
    return r;
}

// ---------------------------------------------------------------------------
// Shared-tile loader: 64x64 float block, row stride ldg (floats).
// Stored as float4 groups with XOR swizzle: phys_group = k4 ^ (row>>2).
// ---------------------------------------------------------------------------
__device__ __forceinline__ void load_tile(float4* s, const float* g, int ldg) {
    int t = threadIdx.x;
#pragma unroll
    for (int i = 0; i < 4; i++) {
        int idx = t + i * TPB;          // 0..1023
        int r  = idx >> 4;              // row 0..63
        int k4 = idx & 15;              // float4 group 0..15
        s[r * 16 + (k4 ^ (r >> 2))] =
            *(const float4*)(g + (size_t)r * ldg + (k4 << 2));
    }
}

__device__ __forceinline__ float getc(const float4& v, int c) {
    return c == 0 ? v.x : c == 1 ? v.y : c == 2 ? v.z : v.w;
}

// ---------------------------------------------------------------------------
// Pack Xh: P0[bh][n][d] = X[b][n][h*64+d]
// ---------------------------------------------------------------------------
__global__ __launch_bounds__(TPB) void pack_kernel(const float* __restrict__ X) {
    int idx = blockIdx.x * TPB + threadIdx.x;        // 0..524287 float4s
    int d4 = idx & 15;
    int n  = (idx >> 4) & (N_ - 1);
    int bh = idx >> 14;
    int b = bh >> 3, h = bh & 7;
    float4 v = *(const float4*)(X + ((size_t)b * N_ + n) * D_ + h * DH_ + (d4 << 2));
    *(float4*)(g_P0 + ((size_t)bh * N_ + n) * DH_ + (d4 << 2)) = v;
}

// ---------------------------------------------------------------------------
// Scores: S[bh][i][j] = <Xh_i, Xh_j> / (8 * clip(tau_h)).  64x64 tile, K=64.
// Variant-1 microkernel, FFMA2 packed along k.
// ---------------------------------------------------------------------------
__global__ __launch_bounds__(TPB) void score_kernel(const float* __restrict__ X,
                                                    const float* __restrict__ temp) {
    __shared__ float4 As[64 * 16], Bs[64 * 16];
    int bh = blockIdx.z, b = bh >> 3, h = bh & 7;
    const float* Xb = X + (size_t)b * N_ * D_ + h * DH_;
    int it = blockIdx.y << 6, jt = blockIdx.x << 6;

    load_tile(As, Xb + (size_t)it * D_, D_);
    load_tile(Bs, Xb + (size_t)jt * D_, D_);
    __syncthreads();

    const u64* As2 = (const u64*)As;
    const u64* Bs2 = (const u64*)Bs;
    int tx = threadIdx.x & 15, ty = threadIdx.x >> 4;
    u64 acc2[4][4];
#pragma unroll
    for (int i = 0; i < 4; i++)
#pragma unroll
        for (int j = 0; j < 4; j++) acc2[i][j] = 0ull;   // (0.f, 0.f)

#pragma unroll
    for (int k4 = 0; k4 < 16; k4++) {
        u64 aL[4], aH[4], bL[4], bH[4];
#pragma unroll
        for (int i = 0; i < 4; i++) {
            int f = ((ty * 4 + i) * 16 + (k4 ^ ty)) * 2;
            aL[i] = As2[f]; aH[i] = As2[f + 1];
        }
#pragma unroll
        for (int j = 0; j < 4; j++) {
            int f = ((tx * 4 + j) * 16 + (k4 ^ tx)) * 2;
            bL[j] = Bs2[f]; bH[j] = Bs2[f + 1];
        }
#pragma unroll
        for (int i = 0; i < 4; i++)
#pragma unroll
            for (int j = 0; j < 4; j++) {
                acc2[i][j] = ffma2(aL[i], bL[j], acc2[i][j]);
                acc2[i][j] = ffma2(aH[i], bH[j], acc2[i][j]);
            }
    }

    float tau = fminf(fmaxf(temp[h], 0.1f), 5.0f);
    float sc = 1.0f / (8.0f * tau);
    float* Srow = g_S + (size_t)bh * N_ * N_;
#pragma unroll
    for (int i = 0; i < 4; i++) {
        float r[4];
#pragma unroll
        for (int j = 0; j < 4; j++) {
            float2 p = unpack2(acc2[i][j]);
            r[j] = (p.x + p.y) * sc;
        }
        *(float4*)(Srow + (size_t)(it + ty * 4 + i) * N_ + jt + tx * 4) =
            make_float4(r[0], r[1], r[2], r[3]);
    }
}

// ---------------------------------------------------------------------------
// Exact top-k threshold + softmax, warp-per-row (bitwise binary search).
// ---------------------------------------------------------------------------
__global__ __launch_bounds__(TPB) void topk_softmax_kernel(const int* __restrict__ layer_idx,
                                                           const int* __restrict__ Lp) {
    int lane = threadIdx.x & 31;
    int gw = blockIdx.x * (TPB / 32) + (threadIdx.x >> 5);  // row id 0..32767
    float* srow = g_S + (size_t)gw * N_;

    unsigned uu[32];
#pragma unroll
    for (int i = 0; i < 32; i++) {
        unsigned bits = __float_as_uint(srow[lane + i * 32]);
        uu[i] = (bits & 0x80000000u) ? ~bits : (bits | 0x80000000u);
    }

    int li = layer_idx[0], Lv = Lp[0];
    double sp = 0.8 + (0.2 - 0.8) * exp(-3.0 * (double)li / (double)Lv);
    int k_val = (int)((1.0 - sp) * (double)N_);
    if (k_val < 1) k_val = 1;
    bool do_thresh = (k_val < N_);

    unsigned T = 0u;
    if (do_thresh) {
#pragma unroll 1
        for (int b = 31; b >= 0; --b) {
            unsigned cand = T | (1u << b);
            int c = 0;
#pragma unroll
            for (int i = 0; i < 32; i++) c += (uu[i] >= cand) ? 1 : 0;
            c = __reduce_add_sync(0xFFFFFFFFu, c);
            if (c >= k_val) T = cand;
        }
    }

    float v[32];
    float vmax = -INFINITY;
#pragma unroll
    for (int i = 0; i < 32; i++) {
        unsigned u = uu[i];
        unsigned bits = (u & 0x80000000u) ? (u ^ 0x80000000u) : ~u;
        v[i] = __uint_as_float(bits);
        vmax = fmaxf(vmax, v[i]);
    }
#pragma unroll
    for (int o = 16; o > 0; o >>= 1)
        vmax = fmaxf(vmax, __shfl_xor_sync(0xFFFFFFFFu, vmax, o));

    float ssum = 0.f;
#pragma unroll
    for (int i = 0; i < 32; i++) {
        bool keep = (!do_thresh) || (uu[i] >= T);
        float ev = keep ? expf(v[i] - vmax) : 0.f;
        v[i] = ev;
        ssum += ev;
    }
#pragma unroll
    for (int o = 16; o > 0; o >>= 1)
        ssum += __shfl_xor_sync(0xFFFFFFFFu, ssum, o);
    float inv = 1.0f / ssum;

#pragma unroll
    for (int i = 0; i < 32; i++) srow[lane + i * 32] = v[i] * inv;
}

// ---------------------------------------------------------------------------
// Hop propagation: Pout = A @ Pin  per (b,h).  M=1024,K=1024,N=64.
// Broadcast-scalar microkernel, FFMA2 packed along output columns.
// ---------------------------------------------------------------------------
__global__ __launch_bounds__(TPB) void spmm_kernel(int in_sel) {
    __shared__ float4 As[64 * 16], Bs[64 * 16];
    int bh = blockIdx.y;
    const float* A    = g_S + (size_t)bh * N_ * N_;
    const float* Pin  = (in_sel ? g_P1 : g_P0) + (size_t)bh * N_ * DH_;
    float*       Pout = (in_sel ? g_P0 : g_P1) + (size_t)bh * N_ * DH_;
    int mt = blockIdx.x << 6;
    int tx = threadIdx.x & 15, ty = threadIdx.x >> 4;
    const u64* Bs2 = (const u64*)Bs;

    u64 acc2[4][2];
#pragma unroll
    for (int i = 0; i < 4; i++) { acc2[i][0] = 0ull; acc2[i][1] = 0ull; }

    for (int kc = 0; kc < 16; kc++) {
        load_tile(As, A + (size_t)mt * N_ + kc * 64, N_);
        load_tile(Bs, Pin + (size_t)(kc * 64) * DH_, DH_);
        __syncthreads();
#pragma unroll
        for (int k4 = 0; k4 < 16; k4++) {
            float4 a[4];
#pragma unroll
            for (int i = 0; i < 4; i++) a[i] = As[(ty * 4 + i) * 16 + (k4 ^ ty)];
#pragma unroll
            for (int c = 0; c < 4; c++) {
                int f = ((k4 * 4 + c) * 16 + (tx ^ k4)) * 2;
                u64 bL = Bs2[f], bH = Bs2[f + 1];
#pragma unroll
                for (int i = 0; i < 4; i++) {
                    u64 s2 = dup2(getc(a[i], c));
                    acc2[i][0] = ffma2(s2, bL, acc2[i][0]);
                    acc2[i][1] = ffma2(s2, bH, acc2[i][1]);
                }
            }
        }
        __syncthreads();
    }
#pragma unroll
    for (int i = 0; i < 4; i++) {
        float2 p0 = unpack2(acc2[i][0]);
        float2 p1 = unpack2(acc2[i][1]);
        *(float4*)(Pout + (size_t)(mt + ty * 4 + i) * DH_ + tx * 4) =
            make_float4(p0.x, p0.y, p1.x, p1.y);
    }
}

// ---------------------------------------------------------------------------
// Filter: H[b, n, h*64+e] (+)= alpha[h,hop] * sum_d P[bh][n][d] * W[h,hop][d][e]
// ---------------------------------------------------------------------------
__global__ __launch_bounds__(TPB) void filter_kernel(const float* __restrict__ Wf,
                                                     const float* __restrict__ alpha,
                                                     int hop) {
    __shared__ float4 As[64 * 16], Bs[64 * 16];
    int bh = blockIdx.y, b = bh >> 3, h = bh & 7;
    const float* Pin = ((hop & 1) ? g_P1 : g_P0) + (size_t)bh * N_ * DH_;
    const float* W   = Wf + (size_t)(h * (KHOP + 1) + hop) * DH_ * DH_;
    int mt = blockIdx.x << 6;
    int tx = threadIdx.x & 15, ty = threadIdx.x >> 4;
    const u64* Bs2 = (const u64*)Bs;

    load_tile(As, Pin + (size_t)mt * DH_, DH_);
    load_tile(Bs, W, DH_);
    __syncthreads();

    u64 acc2[4][2];
#pragma unroll
    for (int i = 0; i < 4; i++) { acc2[i][0] = 0ull; acc2[i][1] = 0ull; }

#pragma unroll
    for (int k4 = 0; k4 < 16; k4++) {
        float4 a[4];
#pragma unroll
        for (int i = 0; i < 4; i++) a[i] = As[(ty * 4 + i) * 16 + (k4 ^ ty)];
#pragma unroll
        for (int c = 0; c < 4; c++) {
            int f = ((k4 * 4 + c) * 16 + (tx ^ k4)) * 2;
            u64 bL = Bs2[f], bH = Bs2[f + 1];
#pragma unroll
            for (int i = 0; i < 4; i++) {
                u64 s2 = dup2(getc(a[i], c));
                acc2[i][0] = ffma2(s2, bL, acc2[i][0]);
                acc2[i][1] = ffma2(s2, bH, acc2[i][1]);
            }
        }
    }

    float av = alpha[h * (KHOP + 1) + hop];
    float* Hb = g_H + ((size_t)(b * N_ + mt)) * D_ + h * DH_;
#pragma unroll
    for (int i = 0; i < 4; i++) {
        float2 p0 = unpack2(acc2[i][0]);
        float2 p1 = unpack2(acc2[i][1]);
        float4 o = make_float4(p0.x * av, p0.y * av, p1.x * av, p1.y * av);
        float4* dst = (float4*)(Hb + (size_t)(ty * 4 + i) * D_ + tx * 4);
        if (hop == 0) {
            *dst = o;
        } else {
            float4 p = *dst;
            p.x += o.x; p.y += o.y; p.z += o.z; p.w += o.w;
            *dst = p;
        }
    }
}

// ---------------------------------------------------------------------------
// Projection: out[i][j] = sum_d H[i][d] * W_proj[j][d] + b_proj[j]
// M=4096, N=512, K=512.  Variant-1 microkernel, FFMA2 packed along k.
// ---------------------------------------------------------------------------
__global__ __launch_bounds__(TPB) void proj_kernel(const float* __restrict__ Wp,
                                                   const float* __restrict__ bias,
                                                   float* __restrict__ out) {
    __shared__ float4 As[64 * 16], Bs[64 * 16];
    int it = blockIdx.y << 6;   // row tile (0..4095)
    int jt = blockIdx.x << 6;   // col tile (0..511)
    int tx = threadIdx.x & 15, ty = threadIdx.x >> 4;
    const u64* As2 = (const u64*)As;
    const u64* Bs2 = (const u64*)Bs;

    u64 acc2[4][4];
#pragma unroll
    for (int i = 0; i < 4; i++)
#pragma unroll
        for (int j = 0; j < 4; j++) acc2[i][j] = 0ull;

    for (int kc = 0; kc < 8; kc++) {
        load_tile(As, g_H + (size_t)it * D_ + kc * 64, D_);
        load_tile(Bs, Wp + (size_t)jt * D_ + kc * 64, D_);
        __syncthreads();
#pragma unroll
        for (int k4 = 0; k4 < 16; k4++) {
            u64 aL[4], aH[4], bL[4], bH[4];
#pragma unroll
            for (int i = 0; i < 4; i++) {
                int f = ((ty * 4 + i) * 16 + (k4 ^ ty)) * 2;
                aL[i] = As2[f]; aH[i] = As2[f + 1];
            }
#pragma unroll
            for (int j = 0; j < 4; j++) {
                int f = ((tx * 4 + j) * 16 + (k4 ^ tx)) * 2;
                bL[j] = Bs2[f]; bH[j] = Bs2[f + 1];
            }
#pragma unroll
            for (int i = 0; i < 4; i++)
#pragma unroll
                for (int j = 0; j < 4; j++) {
                    acc2[i][j] = ffma2(aL[i], bL[j], acc2[i][j]);
                    acc2[i][j] = ffma2(aH[i], bH[j], acc2[i][j]);
                }
        }
        __syncthreads();
    }

    float4 bb4 = *(const float4*)(bias + jt + tx * 4);
#pragma unroll
    for (int i = 0; i < 4; i++) {
        float r[4];
#pragma unroll
        for (int j = 0; j < 4; j++) {
            float2 p = unpack2(acc2[i][j]);
            r[j] = p.x + p.y;
        }
        *(float4*)(out + (size_t)(it + ty * 4 + i) * D_ + jt + tx * 4) =
            make_float4(r[0] + bb4.x, r[1] + bb4.y, r[2] + bb4.z, r[3] + bb4.w);
    }
}

}  // namespace

extern "C" void kernel_launch(void* const* d_in, const int* in_sizes, int n_in,
                              void* d_out, int out_size) {
    const float* X           = (const float*)d_in[0];
    const float* temperature = (const float*)d_in[1];
    const float* W_filt      = (const float*)d_in[2];
    const float* alpha       = (const float*)d_in[3];
    const float* W_proj      = (const float*)d_in[4];
    const float* b_proj      = (const float*)d_in[5];
    const int*   layer_idx   = (const int*)d_in[6];
    const int*   Lp          = (const int*)d_in[7];
    float* out = (float*)d_out;
    (void)in_sizes; (void)n_in; (void)out_size;

    // 1) Pack Xh -> P0
    pack_kernel<<<2048, TPB>>>(X);
    // 2) Per-head scaled scores S (overwritten to adjacency A in step 3)
    score_kernel<<<dim3(16, 16, 32), TPB>>>(X, temperature);
    // 3) Exact top-k threshold + row softmax (in-place on g_S)
    topk_softmax_kernel<<<4096, TPB>>>(layer_idx, Lp);
    // 4) Hop 0 filter contribution (initializes H)
    filter_kernel<<<dim3(16, 32), TPB>>>(W_filt, alpha, 0);
    // 5) Hops 1..3: propagate then accumulate filter
    for (int k = 1; k <= KHOP; k++) {
        spmm_kernel<<<dim3(16, 32), TPB>>>((k - 1) & 1);
        filter_kernel<<<dim3(16, 32), TPB>>>(W_filt, alpha, k);
    }
    // 6) Output projection + bias
    proj_kernel<<<dim3(8, 64), TPB>>>(W_proj, b_proj, out);
}

// round 3
// speedup vs baseline: 1.2110x; 1.1140x over previous
#include <cuda_runtime.h>
#include <math.h>

#define TPB 256

namespace {

constexpr int B_ = 4, N_ = 1024, D_ = 512, H_ = 8, DH_ = 64, BH_ = 32, KHOP = 3;

using u64 = unsigned long long;

// Device-global scratch (no allocations allowed)
__device__ float g_S[(size_t)BH_ * N_ * N_];              // 128 MB scores -> adjacency
__device__ float g_P[KHOP + 1][(size_t)BH_ * N_ * DH_];   // 4 x 8 MB hop buffers
__device__ float g_H[(size_t)B_ * N_ * D_];               // 8 MB filtered output

// ---------------------------------------------------------------------------
// Packed f32x2 helpers
// ---------------------------------------------------------------------------
__device__ __forceinline__ u64 ffma2(u64 a, u64 b, u64 c) {
    u64 d;
    asm("fma.rn.f32x2 %0, %1, %2, %3;" : "=l"(d) : "l"(a), "l"(b), "l"(c));
    return d;
}
__device__ __forceinline__ u64 dup2(float s) {
    u64 d;
    asm("mov.b64 %0, {%1, %1};" : "=l"(d) : "f"(s));
    return d;
}
__device__ __forceinline__ float2 unpack2(u64 v) {
    float2 r;
    asm("mov.b64 {%0, %1}, %2;" : "=f"(r.x), "=f"(r.y) : "l"(v));
    return r;
}

// ---------------------------------------------------------------------------
// Tile I/O: 64x64 float tile as float4 groups, XOR swizzle phys = k4 ^ (r>>2)
// Split into LDG (into regs) and STS (regs -> smem) for pipelining.
// ---------------------------------------------------------------------------
__device__ __forceinline__ void ldg_tile(float4 r[4], const float* g, int ldg) {
    int t = threadIdx.x;
#pragma unroll
    for (int i = 0; i < 4; i++) {
        int idx = t + i * TPB;
        int rr = idx >> 4, k4 = idx & 15;
        r[i] = *(const float4*)(g + (size_t)rr * ldg + (k4 << 2));
    }
}
__device__ __forceinline__ void sts_tile(float4* s, const float4 r[4]) {
    int t = threadIdx.x;
#pragma unroll
    for (int i = 0; i < 4; i++) {
        int idx = t + i * TPB;
        int rr = idx >> 4, k4 = idx & 15;
        s[rr * 16 + (k4 ^ (rr >> 2))] = r[i];
    }
}
__device__ __forceinline__ void load_tile(float4* s, const float* g, int ldg) {
    float4 r[4];
    ldg_tile(r, g, ldg);
    sts_tile(s, r);
}

__device__ __forceinline__ float getc(const float4& v, int c) {
    return c == 0 ? v.x : c == 1 ? v.y : c == 2 ? v.z : v.w;
}

// ---------------------------------------------------------------------------
// Pack Xh: P[0][bh][n][d] = X[b][n][h*64+d]
// ---------------------------------------------------------------------------
__global__ __launch_bounds__(TPB) void pack_kernel(const float* __restrict__ X) {
    int idx = blockIdx.x * TPB + threadIdx.x;
    int d4 = idx & 15;
    int n  = (idx >> 4) & (N_ - 1);
    int bh = idx >> 14;
    int b = bh >> 3, h = bh & 7;
    float4 v = *(const float4*)(X + ((size_t)b * N_ + n) * D_ + h * DH_ + (d4 << 2));
    *(float4*)(&g_P[0][((size_t)bh * N_ + n) * DH_ + (d4 << 2)]) = v;
}

// ---------------------------------------------------------------------------
// Scores: S[bh][i][j] = <Xh_i, Xh_j> / (8 * clip(tau_h)).  64x64 tile, K=64.
// ---------------------------------------------------------------------------
__global__ __launch_bounds__(TPB) void score_kernel(const float* __restrict__ X,
                                                    const float* __restrict__ temp) {
    __shared__ float4 As[64 * 16], Bs[64 * 16];
    int bh = blockIdx.z, b = bh >> 3, h = bh & 7;
    const float* Xb = X + (size_t)b * N_ * D_ + h * DH_;
    int it = blockIdx.y << 6, jt = blockIdx.x << 6;

    load_tile(As, Xb + (size_t)it * D_, D_);
    load_tile(Bs, Xb + (size_t)jt * D_, D_);
    __syncthreads();

    const u64* As2 = (const u64*)As;
    const u64* Bs2 = (const u64*)Bs;
    int tx = threadIdx.x & 15, ty = threadIdx.x >> 4;
    u64 acc2[4][4];
#pragma unroll
    for (int i = 0; i < 4; i++)
#pragma unroll
        for (int j = 0; j < 4; j++) acc2[i][j] = 0ull;

#pragma unroll
    for (int k4 = 0; k4 < 16; k4++) {
        u64 aL[4], aH[4], bL[4], bH[4];
#pragma unroll
        for (int i = 0; i < 4; i++) {
            int f = ((ty * 4 + i) * 16 + (k4 ^ ty)) * 2;
            aL[i] = As2[f]; aH[i] = As2[f + 1];
        }
#pragma unroll
        for (int j = 0; j < 4; j++) {
            int f = ((tx * 4 + j) * 16 + (k4 ^ tx)) * 2;
            bL[j] = Bs2[f]; bH[j] = Bs2[f + 1];
        }
#pragma unroll
        for (int i = 0; i < 4; i++)
#pragma unroll
            for (int j = 0; j < 4; j++) {
                acc2[i][j] = ffma2(aL[i], bL[j], acc2[i][j]);
                acc2[i][j] = ffma2(aH[i], bH[j], acc2[i][j]);
            }
    }

    float tau = fminf(fmaxf(temp[h], 0.1f), 5.0f);
    float sc = 1.0f / (8.0f * tau);
    float* Srow = g_S + (size_t)bh * N_ * N_;
#pragma unroll
    for (int i = 0; i < 4; i++) {
        float r[4];
#pragma unroll
        for (int j = 0; j < 4; j++) {
            float2 p = unpack2(acc2[i][j]);
            r[j] = (p.x + p.y) * sc;
        }
        *(float4*)(Srow + (size_t)(it + ty * 4 + i) * N_ + jt + tx * 4) =
            make_float4(r[0], r[1], r[2], r[3]);
    }
}

// ---------------------------------------------------------------------------
// Exact top-k threshold + softmax, warp-per-row.
// Two-phase exact select: 16-bit prefix binary search, then max-extraction
// among prefix-matching keys. Exact k-th largest value -> same tie semantics
// as jnp.where(S < thresh, -inf, S).
// ---------------------------------------------------------------------------
__global__ __launch_bounds__(TPB) void topk_softmax_kernel(const int* __restrict__ layer_idx,
                                                           const int* __restrict__ Lp) {
    int lane = threadIdx.x & 31;
    size_t row = (size_t)blockIdx.x * (TPB / 32) + (threadIdx.x >> 5);
    float4* s4 = (float4*)(g_S + row * N_);

    float4 d4v[8];
#pragma unroll
    for (int i = 0; i < 8; i++) d4v[i] = s4[lane + i * 32];

    unsigned uu[32];
#pragma unroll
    for (int i = 0; i < 8; i++) {
        const float* f = (const float*)&d4v[i];
#pragma unroll
        for (int j = 0; j < 4; j++) {
            unsigned bits = __float_as_uint(f[j]);
            uu[i * 4 + j] = (bits & 0x80000000u) ? ~bits : (bits | 0x80000000u);
        }
    }

    int li = layer_idx[0], Lv = Lp[0];
    double sp = 0.8 + (0.2 - 0.8) * exp(-3.0 * (double)li / (double)Lv);
    int k_val = (int)((1.0 - sp) * (double)N_);
    if (k_val < 1) k_val = 1;
    bool do_thresh = (k_val < N_);

    unsigned T = 0u;
    if (do_thresh) {
        unsigned hi[32];
#pragma unroll
        for (int i = 0; i < 32; i++) hi[i] = uu[i] >> 16;

        // Phase 1: P = high-16 bits of the k-th largest key.
        unsigned P = 0u;
#pragma unroll 1
        for (int b = 15; b >= 0; --b) {
            unsigned cand = P | (1u << b);
            int c = 0;
#pragma unroll
            for (int i = 0; i < 32; i++) c += (hi[i] >= cand) ? 1 : 0;
            if (__reduce_add_sync(0xFFFFFFFFu, c) >= k_val) P = cand;
        }

        int cgt = 0;
#pragma unroll
        for (int i = 0; i < 32; i++) cgt += (hi[i] > P) ? 1 : 0;
        cgt = __reduce_add_sync(0xFFFFFFFFu, cgt);
        int j = k_val - cgt;  // rank needed within prefix-P keys (>= 1)

        // Phase 2: j-th largest low-16 among keys with hi == P.
        unsigned act = 0u;
        unsigned lo[32];
#pragma unroll
        for (int i = 0; i < 32; i++) {
            lo[i] = uu[i] & 0xFFFFu;
            if (hi[i] == P) act |= (1u << i);
        }
        unsigned Mfin = 0u;
#pragma unroll 1
        while (true) {
            unsigned m = 0u;
#pragma unroll
            for (int i = 0; i < 32; i++)
                if (act & (1u << i)) m = m > lo[i] ? m : lo[i];
            m = __reduce_max_sync(0xFFFFFFFFu, m);
            int q = 0;
            unsigned hitm = 0u;
#pragma unroll
            for (int i = 0; i < 32; i++)
                if ((act & (1u << i)) && lo[i] == m) { q++; hitm |= (1u << i); }
            q = __reduce_add_sync(0xFFFFFFFFu, q);
            if (j <= q) { Mfin = m; break; }
            j -= q;
            act &= ~hitm;
        }
        T = (P << 16) | Mfin;
    }

    // Softmax with threshold mask.
    float v[32];
    float vmax = -INFINITY;
#pragma unroll
    for (int i = 0; i < 32; i++) {
        unsigned u = uu[i];
        unsigned bits = (u & 0x80000000u) ? (u ^ 0x80000000u) : ~u;
        v[i] = __uint_as_float(bits);
        vmax = fmaxf(vmax, v[i]);
    }
#pragma unroll
    for (int o = 16; o > 0; o >>= 1)
        vmax = fmaxf(vmax, __shfl_xor_sync(0xFFFFFFFFu, vmax, o));

    float ssum = 0.f;
#pragma unroll
    for (int i = 0; i < 32; i++) {
        bool keep = (!do_thresh) || (uu[i] >= T);
        float ev = keep ? expf(v[i] - vmax) : 0.f;
        v[i] = ev;
        ssum += ev;
    }
#pragma unroll
    for (int o = 16; o > 0; o >>= 1)
        ssum += __shfl_xor_sync(0xFFFFFFFFu, ssum, o);
    float inv = 1.0f / ssum;

#pragma unroll
    for (int i = 0; i < 8; i++) {
        float* f = (float*)&d4v[i];
#pragma unroll
        for (int jj = 0; jj < 4; jj++) f[jj] = v[i * 4 + jj] * inv;
        s4[lane + i * 32] = d4v[i];
    }
}

// ---------------------------------------------------------------------------
// Hop propagation: P[hop] = A @ P[hop-1]  per (b,h).  M=1024,K=1024,N=64.
// Double-buffered smem pipeline: prefetch chunk kc+1 during compute of kc.
// ---------------------------------------------------------------------------
__global__ __launch_bounds__(TPB, 2) void spmm_kernel(int hop) {
    __shared__ float4 As[2][64 * 16], Bs[2][64 * 16];
    int bh = blockIdx.y;
    const float* A    = g_S + (size_t)bh * N_ * N_;
    const float* Pin  = &g_P[hop - 1][(size_t)bh * N_ * DH_];
    float*       Pout = &g_P[hop    ][(size_t)bh * N_ * DH_];
    int mt = blockIdx.x << 6;
    int tx = threadIdx.x & 15, ty = threadIdx.x >> 4;

    float4 ra[4], rb[4];
    ldg_tile(ra, A + (size_t)mt * N_, N_);
    ldg_tile(rb, Pin, DH_);
    sts_tile(As[0], ra);
    sts_tile(Bs[0], rb);
    __syncthreads();

    u64 acc2[4][2];
#pragma unroll
    for (int i = 0; i < 4; i++) { acc2[i][0] = 0ull; acc2[i][1] = 0ull; }

#pragma unroll 1
    for (int kc = 0; kc < 16; kc++) {
        int cur = kc & 1, nxt = cur ^ 1;
        if (kc < 15) {
            ldg_tile(ra, A + (size_t)mt * N_ + (kc + 1) * 64, N_);
            ldg_tile(rb, Pin + (size_t)((kc + 1) * 64) * DH_, DH_);
        }
        const float4* Ac = As[cur];
        const u64*   Bc2 = (const u64*)Bs[cur];
#pragma unroll
        for (int k4 = 0; k4 < 16; k4++) {
            float4 a[4];
#pragma unroll
            for (int i = 0; i < 4; i++) a[i] = Ac[(ty * 4 + i) * 16 + (k4 ^ ty)];
#pragma unroll
            for (int c = 0; c < 4; c++) {
                int f = ((k4 * 4 + c) * 16 + (tx ^ k4)) * 2;
                u64 bL = Bc2[f], bH = Bc2[f + 1];
#pragma unroll
                for (int i = 0; i < 4; i++) {
                    u64 s2 = dup2(getc(a[i], c));
                    acc2[i][0] = ffma2(s2, bL, acc2[i][0]);
                    acc2[i][1] = ffma2(s2, bH, acc2[i][1]);
                }
            }
        }
        if (kc < 15) {
            sts_tile(As[nxt], ra);
            sts_tile(Bs[nxt], rb);
        }
        __syncthreads();
    }

#pragma unroll
    for (int i = 0; i < 4; i++) {
        float2 p0 = unpack2(acc2[i][0]);
        float2 p1 = unpack2(acc2[i][1]);
        *(float4*)(Pout + (size_t)(mt + ty * 4 + i) * DH_ + tx * 4) =
            make_float4(p0.x, p0.y, p1.x, p1.y);
    }
}

// ---------------------------------------------------------------------------
// Fused filter: H[b,n,h*64+e] = sum_{hop=0..3} alpha[h,hop] *
//                               sum_d P[hop][bh][n][d] * W[h,hop][d][e]
// One GEMM with K = 4 chunks (one per hop), alpha applied at SMEM store.
// ---------------------------------------------------------------------------
__global__ __launch_bounds__(TPB, 2) void filter_kernel(const float* __restrict__ Wf,
                                                        const float* __restrict__ alpha) {
    __shared__ float4 As[2][64 * 16], Bs[2][64 * 16];
    int bh = blockIdx.y, b = bh >> 3, h = bh & 7;
    int mt = blockIdx.x << 6;
    int tx = threadIdx.x & 15, ty = threadIdx.x >> 4;

    float av[KHOP + 1];
#pragma unroll
    for (int k = 0; k <= KHOP; k++) av[k] = alpha[h * (KHOP + 1) + k];

    float4 ra[4], rb[4];
    ldg_tile(ra, &g_P[0][(size_t)bh * N_ * DH_ + (size_t)mt * DH_], DH_);
    ldg_tile(rb, Wf + (size_t)(h * (KHOP + 1)) * DH_ * DH_, DH_);
#pragma unroll
    for (int i = 0; i < 4; i++) {
        rb[i].x *= av[0]; rb[i].y *= av[0]; rb[i].z *= av[0]; rb[i].w *= av[0];
    }
    sts_tile(As[0], ra);
    sts_tile(Bs[0], rb);
    __syncthreads();

    u64 acc2[4][2];
#pragma unroll
    for (int i = 0; i < 4; i++) { acc2[i][0] = 0ull; acc2[i][1] = 0ull; }

#pragma unroll 1
    for (int hop = 0; hop <= KHOP; hop++) {
        int cur = hop & 1, nxt = cur ^ 1;
        if (hop < KHOP) {
            ldg_tile(ra, &g_P[hop + 1][(size_t)bh * N_ * DH_ + (size_t)mt * DH_], DH_);
            ldg_tile(rb, Wf + (size_t)(h * (KHOP + 1) + hop + 1) * DH_ * DH_, DH_);
            float a1 = av[hop + 1];
#pragma unroll
            for (int i = 0; i < 4; i++) {
                rb[i].x *= a1; rb[i].y *= a1; rb[i].z *= a1; rb[i].w *= a1;
            }
        }
        const float4* Ac = As[cur];
        const u64*   Bc2 = (const u64*)Bs[cur];
#pragma unroll
        for (int k4 = 0; k4 < 16; k4++) {
            float4 a[4];
#pragma unroll
            for (int i = 0; i < 4; i++) a[i] = Ac[(ty * 4 + i) * 16 + (k4 ^ ty)];
#pragma unroll
            for (int c = 0; c < 4; c++) {
                int f = ((k4 * 4 + c) * 16 + (tx ^ k4)) * 2;
                u64 bL = Bc2[f], bH = Bc2[f + 1];
#pragma unroll
                for (int i = 0; i < 4; i++) {
                    u64 s2 = dup2(getc(a[i], c));
                    acc2[i][0] = ffma2(s2, bL, acc2[i][0]);
                    acc2[i][1] = ffma2(s2, bH, acc2[i][1]);
                }
            }
        }
        if (hop < KHOP) {
            sts_tile(As[nxt], ra);
            sts_tile(Bs[nxt], rb);
        }
        __syncthreads();
    }

    float* Hb = g_H + ((size_t)(b * N_ + mt)) * D_ + h * DH_;
#pragma unroll
    for (int i = 0; i < 4; i++) {
        float2 p0 = unpack2(acc2[i][0]);
        float2 p1 = unpack2(acc2[i][1]);
        *(float4*)(Hb + (size_t)(ty * 4 + i) * D_ + tx * 4) =
            make_float4(p0.x, p0.y, p1.x, p1.y);
    }
}

// ---------------------------------------------------------------------------
// Projection: out[i][j] = sum_d H[i][d] * W_proj[j][d] + b_proj[j]
// ---------------------------------------------------------------------------
__global__ __launch_bounds__(TPB) void proj_kernel(const float* __restrict__ Wp,
                                                   const float* __restrict__ bias,
                                                   float* __restrict__ out) {
    __shared__ float4 As[64 * 16], Bs[64 * 16];
    int it = blockIdx.y << 6;
    int jt = blockIdx.x << 6;
    int tx = threadIdx.x & 15, ty = threadIdx.x >> 4;
    const u64* As2 = (const u64*)As;
    const u64* Bs2 = (const u64*)Bs;

    u64 acc2[4][4];
#pragma unroll
    for (int i = 0; i < 4; i++)
#pragma unroll
        for (int j = 0; j < 4; j++) acc2[i][j] = 0ull;

    for (int kc = 0; kc < 8; kc++) {
        load_tile(As, g_H + (size_t)it * D_ + kc * 64, D_);
        load_tile(Bs, Wp + (size_t)jt * D_ + kc * 64, D_);
        __syncthreads();
#pragma unroll
        for (int k4 = 0; k4 < 16; k4++) {
            u64 aL[4], aH[4], bL[4], bH[4];
#pragma unroll
            for (int i = 0; i < 4; i++) {
                int f = ((ty * 4 + i) * 16 + (k4 ^ ty)) * 2;
                aL[i] = As2[f]; aH[i] = As2[f + 1];
            }
#pragma unroll
            for (int j = 0; j < 4; j++) {
                int f = ((tx * 4 + j) * 16 + (k4 ^ tx)) * 2;
                bL[j] = Bs2[f]; bH[j] = Bs2[f + 1];
            }
#pragma unroll
            for (int i = 0; i < 4; i++)
#pragma unroll
                for (int j = 0; j < 4; j++) {
                    acc2[i][j] = ffma2(aL[i], bL[j], acc2[i][j]);
                    acc2[i][j] = ffma2(aH[i], bH[j], acc2[i][j]);
                }
        }
        __syncthreads();
    }

    float4 bb4 = *(const float4*)(bias + jt + tx * 4);
#pragma unroll
    for (int i = 0; i < 4; i++) {
        float r[4];
#pragma unroll
        for (int j = 0; j < 4; j++) {
            float2 p = unpack2(acc2[i][j]);
            r[j] = p.x + p.y;
        }
        *(float4*)(out + (size_t)(it + ty * 4 + i) * D_ + jt + tx * 4) =
            make_float4(r[0] + bb4.x, r[1] + bb4.y, r[2] + bb4.z, r[3] + bb4.w);
    }
}

}  // namespace

extern "C" void kernel_launch(void* const* d_in, const int* in_sizes, int n_in,
                              void* d_out, int out_size) {
    const float* X           = (const float*)d_in[0];
    const float* temperature = (const float*)d_in[1];
    const float* W_filt      = (const float*)d_in[2];
    const float* alpha       = (const float*)d_in[3];
    const float* W_proj      = (const float*)d_in[4];
    const float* b_proj      = (const float*)d_in[5];
    const int*   layer_idx   = (const int*)d_in[6];
    const int*   Lp          = (const int*)d_in[7];
    float* out = (float*)d_out;
    (void)in_sizes; (void)n_in; (void)out_size;

    // 1) Pack Xh -> P[0]
    pack_kernel<<<2048, TPB>>>(X);
    // 2) Per-head scaled scores S
    score_kernel<<<dim3(16, 16, 32), TPB>>>(X, temperature);
    // 3) Exact top-k threshold + row softmax (in-place on g_S)
    topk_softmax_kernel<<<4096, TPB>>>(layer_idx, Lp);
    // 4) Hops 1..3: P[k] = A @ P[k-1] (double-buffered pipeline)
    for (int k = 1; k <= KHOP; k++)
        spmm_kernel<<<dim3(16, 32), TPB>>>(k);
    // 5) Fused 4-hop filter -> H
    filter_kernel<<<dim3(16, 32), TPB>>>(W_filt, alpha);
    // 6) Output projection + bias
    proj_kernel<<<dim3(8, 64), TPB>>>(W_proj, b_proj, out);
}

// round 5
// speedup vs baseline: 1.8645x; 1.5396x over previous
#include <cuda_runtime.h>
#include <cuda_bf16.h>
#include <math.h>
#include <stdint.h>

#define TPB 256

namespace {

constexpr int B_ = 4, N_ = 1024, D_ = 512, H_ = 8, DH_ = 64, BH_ = 32, KHOP = 3;

using u64 = unsigned long long;

// Device-global scratch (no allocations allowed)
__device__ float g_S[(size_t)BH_ * N_ * N_];                 // 128 MB fp32 scores
__device__ __nv_bfloat16 g_Ahi[(size_t)BH_ * N_ * N_];       // 64 MB adjacency hi
__device__ __nv_bfloat16 g_Alo[(size_t)BH_ * N_ * N_];       // 64 MB adjacency lo
__device__ __nv_bfloat16 g_PThi[(size_t)BH_ * DH_ * N_];     // 4 MB  P^T hi
__device__ __nv_bfloat16 g_PTlo[(size_t)BH_ * DH_ * N_];     // 4 MB  P^T lo
__device__ float g_P[KHOP + 1][(size_t)BH_ * N_ * DH_];      // 4 x 8 MB hop buffers
__device__ float g_H[(size_t)B_ * N_ * D_];                  // 8 MB filtered output

// ---------------------------------------------------------------------------
// Packed f32x2 helpers (SIMT GEMMs)
// ---------------------------------------------------------------------------
__device__ __forceinline__ u64 ffma2(u64 a, u64 b, u64 c) {
    u64 d;
    asm("fma.rn.f32x2 %0, %1, %2, %3;" : "=l"(d) : "l"(a), "l"(b), "l"(c));
    return d;
}
__device__ __forceinline__ u64 dup2(float s) {
    u64 d;
    asm("mov.b64 %0, {%1, %1};" : "=l"(d) : "f"(s));
    return d;
}
__device__ __forceinline__ float2 unpack2(u64 v) {
    float2 r;
    asm("mov.b64 {%0, %1}, %2;" : "=f"(r.x), "=f"(r.y) : "l"(v));
    return r;
}

// ---------------------------------------------------------------------------
// cp.async + ldmatrix + mma.sync helpers (all valid on compute_103)
// ---------------------------------------------------------------------------
__device__ __forceinline__ uint32_t smem_u32(const void* p) {
    return (uint32_t)__cvta_generic_to_shared(p);
}
__device__ __forceinline__ void cp16(uint32_t s, const void* g) {
    asm volatile("cp.async.cg.shared.global [%0], [%1], 16;" :: "r"(s), "l"(g));
}
#define CP_COMMIT() asm volatile("cp.async.commit_group;" ::: "memory")
#define CP_WAIT1()  asm volatile("cp.async.wait_group 1;" ::: "memory")
#define CP_WAIT0()  asm volatile("cp.async.wait_group 0;" ::: "memory")

__device__ __forceinline__ void ldsm4(uint32_t r[4], uint32_t addr) {
    asm volatile("ldmatrix.sync.aligned.m8n8.x4.shared.b16 {%0,%1,%2,%3}, [%4];"
                 : "=r"(r[0]), "=r"(r[1]), "=r"(r[2]), "=r"(r[3]) : "r"(addr));
}
__device__ __forceinline__ void mma16816(float d[4], const uint32_t a[4],
                                         uint32_t b0, uint32_t b1) {
    asm volatile(
        "mma.sync.aligned.m16n8k16.row.col.f32.bf16.bf16.f32 "
        "{%0,%1,%2,%3}, {%4,%5,%6,%7}, {%8,%9}, {%0,%1,%2,%3};"
        : "+f"(d[0]), "+f"(d[1]), "+f"(d[2]), "+f"(d[3])
        : "r"(a[0]), "r"(a[1]), "r"(a[2]), "r"(a[3]), "r"(b0), "r"(b1));
}

// SMEM layout for spmm_mma: 2 stages x 32KB
constexpr int OFF_AHI = 0;
constexpr int OFF_ALO = 8192;
constexpr int OFF_PHI = 16384;
constexpr int OFF_PLO = 24576;
constexpr int STAGE_BYTES = 32768;
constexpr int SMEM_SPMM = 2 * STAGE_BYTES;   // 64 KB dynamic

// ---------------------------------------------------------------------------
// Tile I/O for SIMT kernels
// ---------------------------------------------------------------------------
__device__ __forceinline__ void ldg_tile(float4 r[4], const float* g, int ldg) {
    int t = threadIdx.x;
#pragma unroll
    for (int i = 0; i < 4; i++) {
        int idx = t + i * TPB;
        int rr = idx >> 4, k4 = idx & 15;
        r[i] = *(const float4*)(g + (size_t)rr * ldg + (k4 << 2));
    }
}
__device__ __forceinline__ void sts_tile(float4* s, const float4 r[4]) {
    int t = threadIdx.x;
#pragma unroll
    for (int i = 0; i < 4; i++) {
        int idx = t + i * TPB;
        int rr = idx >> 4, k4 = idx & 15;
        s[rr * 16 + (k4 ^ (rr >> 2))] = r[i];
    }
}
__device__ __forceinline__ void load_tile(float4* s, const float* g, int ldg) {
    float4 r[4];
    ldg_tile(r, g, ldg);
    sts_tile(s, r);
}
__device__ __forceinline__ float getc(const float4& v, int c) {
    return c == 0 ? v.x : c == 1 ? v.y : c == 2 ? v.z : v.w;
}

// ---------------------------------------------------------------------------
// Pack Xh: P[0][bh][n][d] = X[b][n][h*64+d]
// ---------------------------------------------------------------------------
__global__ __launch_bounds__(TPB) void pack_kernel(const float* __restrict__ X) {
    int idx = blockIdx.x * TPB + threadIdx.x;
    int d4 = idx & 15;
    int n  = (idx >> 4) & (N_ - 1);
    int bh = idx >> 14;
    int b = bh >> 3, h = bh & 7;
    float4 v = *(const float4*)(X + ((size_t)b * N_ + n) * D_ + h * DH_ + (d4 << 2));
    *(float4*)(&g_P[0][((size_t)bh * N_ + n) * DH_ + (d4 << 2)]) = v;
}

// ---------------------------------------------------------------------------
// Scores: S[bh][i][j] = <Xh_i, Xh_j> / (8 * clip(tau_h))
// ---------------------------------------------------------------------------
__global__ __launch_bounds__(TPB) void score_kernel(const float* __restrict__ X,
                                                    const float* __restrict__ temp) {
    __shared__ float4 As[64 * 16], Bs[64 * 16];
    int bh = blockIdx.z, b = bh >> 3, h = bh & 7;
    const float* Xb = X + (size_t)b * N_ * D_ + h * DH_;
    int it = blockIdx.y << 6, jt = blockIdx.x << 6;

    load_tile(As, Xb + (size_t)it * D_, D_);
    load_tile(Bs, Xb + (size_t)jt * D_, D_);
    __syncthreads();

    const u64* As2 = (const u64*)As;
    const u64* Bs2 = (const u64*)Bs;
    int tx = threadIdx.x & 15, ty = threadIdx.x >> 4;
    u64 acc2[4][4];
#pragma unroll
    for (int i = 0; i < 4; i++)
#pragma unroll
        for (int j = 0; j < 4; j++) acc2[i][j] = 0ull;

#pragma unroll
    for (int k4 = 0; k4 < 16; k4++) {
        u64 aL[4], aH[4], bL[4], bH[4];
#pragma unroll
        for (int i = 0; i < 4; i++) {
            int f = ((ty * 4 + i) * 16 + (k4 ^ ty)) * 2;
            aL[i] = As2[f]; aH[i] = As2[f + 1];
        }
#pragma unroll
        for (int j = 0; j < 4; j++) {
            int f = ((tx * 4 + j) * 16 + (k4 ^ tx)) * 2;
            bL[j] = Bs2[f]; bH[j] = Bs2[f + 1];
        }
#pragma unroll
        for (int i = 0; i < 4; i++)
#pragma unroll
            for (int j = 0; j < 4; j++) {
                acc2[i][j] = ffma2(aL[i], bL[j], acc2[i][j]);
                acc2[i][j] = ffma2(aH[i], bH[j], acc2[i][j]);
            }
    }

    float tau = fminf(fmaxf(temp[h], 0.1f), 5.0f);
    float sc = 1.0f / (8.0f * tau);
    float* Srow = g_S + (size_t)bh * N_ * N_;
#pragma unroll
    for (int i = 0; i < 4; i++) {
        float r[4];
#pragma unroll
        for (int j = 0; j < 4; j++) {
            float2 p = unpack2(acc2[i][j]);
            r[j] = (p.x + p.y) * sc;
        }
        *(float4*)(Srow + (size_t)(it + ty * 4 + i) * N_ + jt + tx * 4) =
            make_float4(r[0], r[1], r[2], r[3]);
    }
}

// ---------------------------------------------------------------------------
// Exact top-k threshold + softmax, warp-per-row; emits bf16 hi/lo adjacency.
// ---------------------------------------------------------------------------
__global__ __launch_bounds__(TPB) void topk_softmax_kernel(const int* __restrict__ layer_idx,
                                                           const int* __restrict__ Lp) {
    int lane = threadIdx.x & 31;
    size_t row = (size_t)blockIdx.x * (TPB / 32) + (threadIdx.x >> 5);
    const float4* s4 = (const float4*)(g_S + row * N_);

    float4 d4v[8];
#pragma unroll
    for (int i = 0; i < 8; i++) d4v[i] = s4[lane + i * 32];

    unsigned uu[32];
#pragma unroll
    for (int i = 0; i < 8; i++) {
        const float* f = (const float*)&d4v[i];
#pragma unroll
        for (int j = 0; j < 4; j++) {
            unsigned bits = __float_as_uint(f[j]);
            uu[i * 4 + j] = (bits & 0x80000000u) ? ~bits : (bits | 0x80000000u);
        }
    }

    int li = layer_idx[0], Lv = Lp[0];
    double sp = 0.8 + (0.2 - 0.8) * exp(-3.0 * (double)li / (double)Lv);
    int k_val = (int)((1.0 - sp) * (double)N_);
    if (k_val < 1) k_val = 1;
    bool do_thresh = (k_val < N_);

    unsigned T = 0u;
    if (do_thresh) {
        unsigned hi[32];
#pragma unroll
        for (int i = 0; i < 32; i++) hi[i] = uu[i] >> 16;

        unsigned P = 0u;
#pragma unroll 1
        for (int b = 15; b >= 0; --b) {
            unsigned cand = P | (1u << b);
            int c = 0;
#pragma unroll
            for (int i = 0; i < 32; i++) c += (hi[i] >= cand) ? 1 : 0;
            if (__reduce_add_sync(0xFFFFFFFFu, c) >= k_val) P = cand;
        }

        int cgt = 0;
#pragma unroll
        for (int i = 0; i < 32; i++) cgt += (hi[i] > P) ? 1 : 0;
        cgt = __reduce_add_sync(0xFFFFFFFFu, cgt);
        int j = k_val - cgt;

        unsigned act = 0u;
        unsigned lo[32];
#pragma unroll
        for (int i = 0; i < 32; i++) {
            lo[i] = uu[i] & 0xFFFFu;
            if (hi[i] == P) act |= (1u << i);
        }
        unsigned Mfin = 0u;
#pragma unroll 1
        while (true) {
            unsigned m = 0u;
#pragma unroll
            for (int i = 0; i < 32; i++)
                if (act & (1u << i)) m = m > lo[i] ? m : lo[i];
            m = __reduce_max_sync(0xFFFFFFFFu, m);
            int q = 0;
            unsigned hitm = 0u;
#pragma unroll
            for (int i = 0; i < 32; i++)
                if ((act & (1u << i)) && lo[i] == m) { q++; hitm |= (1u << i); }
            q = __reduce_add_sync(0xFFFFFFFFu, q);
            if (j <= q) { Mfin = m; break; }
            j -= q;
            act &= ~hitm;
        }
        T = (P << 16) | Mfin;
    }

    float v[32];
    float vmax = -INFINITY;
#pragma unroll
    for (int i = 0; i < 32; i++) {
        unsigned u = uu[i];
        unsigned bits = (u & 0x80000000u) ? (u ^ 0x80000000u) : ~u;
        v[i] = __uint_as_float(bits);
        vmax = fmaxf(vmax, v[i]);
    }
#pragma unroll
    for (int o = 16; o > 0; o >>= 1)
        vmax = fmaxf(vmax, __shfl_xor_sync(0xFFFFFFFFu, vmax, o));

    float ssum = 0.f;
#pragma unroll
    for (int i = 0; i < 32; i++) {
        bool keep = (!do_thresh) || (uu[i] >= T);
        float ev = keep ? expf(v[i] - vmax) : 0.f;
        v[i] = ev;
        ssum += ev;
    }
#pragma unroll
    for (int o = 16; o > 0; o >>= 1)
        ssum += __shfl_xor_sync(0xFFFFFFFFu, ssum, o);
    float inv = 1.0f / ssum;

    __nv_bfloat16* ahrow = g_Ahi + row * N_;
    __nv_bfloat16* alrow = g_Alo + row * N_;
#pragma unroll
    for (int i = 0; i < 8; i++) {
        __nv_bfloat16 hh[4], ll[4];
#pragma unroll
        for (int j = 0; j < 4; j++) {
            float p = v[i * 4 + j] * inv;
            __nv_bfloat16 h = __float2bfloat16(p);
            hh[j] = h;
            ll[j] = __float2bfloat16(p - __bfloat162float(h));
        }
        *(uint2*)(ahrow + (lane + i * 32) * 4) = *(const uint2*)hh;
        *(uint2*)(alrow + (lane + i * 32) * 4) = *(const uint2*)ll;
    }
}

// ---------------------------------------------------------------------------
// PT convert: g_P[hop] fp32 [bh][1024k][64n] -> transposed bf16 hi/lo [bh][n][k]
// ---------------------------------------------------------------------------
__global__ __launch_bounds__(128) void pt_convert_kernel(int hop) {
    __shared__ float tile[64][65];
    int kt = blockIdx.x, bh = blockIdx.y;
    const float* src = &g_P[hop][(size_t)bh * N_ * DH_ + (size_t)kt * 64 * DH_];
    int t = threadIdx.x;
#pragma unroll
    for (int i = 0; i < 8; i++) {
        int idx = t + i * 128;
        int r = idx >> 4, c4 = idx & 15;
        float4 v = *(const float4*)(src + (size_t)r * DH_ + c4 * 4);
        tile[r][c4 * 4 + 0] = v.x;
        tile[r][c4 * 4 + 1] = v.y;
        tile[r][c4 * 4 + 2] = v.z;
        tile[r][c4 * 4 + 3] = v.w;
    }
    __syncthreads();
    int n = t >> 1, kh = (t & 1) * 32;
    __nv_bfloat16 hi[32], lo[32];
#pragma unroll
    for (int k = 0; k < 32; k++) {
        float x = tile[kh + k][n];
        __nv_bfloat16 h = __float2bfloat16(x);
        hi[k] = h;
        lo[k] = __float2bfloat16(x - __bfloat162float(h));
    }
    size_t off = ((size_t)bh * DH_ + n) * N_ + kt * 64 + kh;
#pragma unroll
    for (int q = 0; q < 4; q++) {
        *(uint4*)(g_PThi + off + q * 8) = *(const uint4*)(hi + q * 8);
        *(uint4*)(g_PTlo + off + q * 8) = *(const uint4*)(lo + q * 8);
    }
}

// ---------------------------------------------------------------------------
// spmm via mma.sync bf16x3:  P[hop] = A @ P[hop-1]
// CTA: 64 m-rows x 64 n, K=1024 in 16 chunks of 64; 4 warps (m16 each);
// 2-stage cp.async pipeline; ldmatrix with XOR chunk swizzle.
// Smem tile rows are 64 halves = 128 B = 8 chunks of 16 B; chunk c of row r
// stored at chunk (c ^ (r & 7)) -> conflict-free ldmatrix.
// ---------------------------------------------------------------------------
__device__ __forceinline__ void spmm_load_chunk(
    uint32_t st, const __nv_bfloat16* Ahi, const __nv_bfloat16* Alo,
    const __nv_bfloat16* Phi, const __nv_bfloat16* Plo, int mt, int k0)
{
    int t = threadIdx.x;
#pragma unroll
    for (int i = 0; i < 4; i++) {
        int idx = t + i * 128;               // 0..511
        int r = idx >> 3, g = idx & 7;
        uint32_t so = (uint32_t)(r * 128 + ((g ^ (r & 7)) << 4));
        size_t go = ((size_t)(mt + r) * N_ + k0 + g * 8) * 2;  // bytes
        cp16(st + OFF_AHI + so, (const char*)Ahi + go);
        cp16(st + OFF_ALO + so, (const char*)Alo + go);
        size_t gp = ((size_t)r * N_ + k0 + g * 8) * 2;
        cp16(st + OFF_PHI + so, (const char*)Phi + gp);
        cp16(st + OFF_PLO + so, (const char*)Plo + gp);
    }
}

__global__ __launch_bounds__(128, 2) void spmm_mma_kernel(int hop) {
    extern __shared__ __align__(1024) char dsm[];
    uint32_t sb = smem_u32(dsm);
    int tid = threadIdx.x, lane = tid & 31, w = tid >> 5;
    int mt = blockIdx.x << 6;            // m-tile of 64
    int bh = blockIdx.y;

    const __nv_bfloat16* Ahi = g_Ahi + (size_t)bh * N_ * N_;
    const __nv_bfloat16* Alo = g_Alo + (size_t)bh * N_ * N_;
    const __nv_bfloat16* Phi = g_PThi + (size_t)bh * DH_ * N_;
    const __nv_bfloat16* Plo = g_PTlo + (size_t)bh * DH_ * N_;
    float* Pout = &g_P[hop][(size_t)bh * N_ * DH_];

    // Per-thread ldmatrix row geometry (constant across k)
    int lr = lane & 7, sel = lane >> 3;
    // A: matrices (m0,klo),(m8,klo),(m0,khi),(m8,khi)
    int amrow = (w << 4) + ((sel & 1) << 3) + lr;
    uint32_t aRowOff = (uint32_t)(amrow * 128);
    int aRowX = amrow & 7;
    int aCsel = sel >> 1;                  // 0: k0-7, 1: k8-15 chunk
    // B: matrices (nlo,klo),(nlo,khi),(nhi,klo),(nhi,khi); n block chosen per p
    int bnrow = ((sel >> 1) << 3) + lr;    // within 16-row n block
    int bCsel = sel & 1;

    float acc[8][4];
#pragma unroll
    for (int j = 0; j < 8; j++)
#pragma unroll
        for (int q = 0; q < 4; q++) acc[j][q] = 0.f;

    spmm_load_chunk(sb, Ahi, Alo, Phi, Plo, mt, 0);
    CP_COMMIT();

#pragma unroll 1
    for (int kc = 0; kc < 16; kc++) {
        uint32_t cur = (uint32_t)(kc & 1) * STAGE_BYTES;
        if (kc < 15) {
            uint32_t nxt = (uint32_t)((kc + 1) & 1) * STAGE_BYTES;
            spmm_load_chunk(sb + nxt, Ahi, Alo, Phi, Plo, mt, (kc + 1) * 64);
            CP_COMMIT();
            CP_WAIT1();
        } else {
            CP_WAIT0();
        }
        __syncthreads();

#pragma unroll
        for (int ks = 0; ks < 4; ks++) {
            uint32_t ahi[4], alo[4];
            {
                int c = 2 * ks + aCsel;
                uint32_t ao = aRowOff + (uint32_t)((c ^ aRowX) << 4);
                ldsm4(ahi, sb + cur + OFF_AHI + ao);
                ldsm4(alo, sb + cur + OFF_ALO + ao);
            }
#pragma unroll
            for (int p = 0; p < 4; p++) {
                int n = (p << 4) + bnrow;
                int c = 2 * ks + bCsel;
                uint32_t bo = (uint32_t)(n * 128 + ((c ^ (n & 7)) << 4));
                uint32_t bhi[4], blo[4];
                ldsm4(bhi, sb + cur + OFF_PHI + bo);
                ldsm4(blo, sb + cur + OFF_PLO + bo);
                mma16816(acc[2 * p],     ahi, bhi[0], bhi[1]);
                mma16816(acc[2 * p],     ahi, blo[0], blo[1]);
                mma16816(acc[2 * p],     alo, bhi[0], bhi[1]);
                mma16816(acc[2 * p + 1], ahi, bhi[2], bhi[3]);
                mma16816(acc[2 * p + 1], ahi, blo[2], blo[3]);
                mma16816(acc[2 * p + 1], alo, bhi[2], bhi[3]);
            }
        }
        __syncthreads();
    }

    // Epilogue: thread holds rows (w*16 + lane/4) and +8; cols j*8 + 2*(lane%4)
    int r0 = mt + (w << 4) + (lane >> 2);
    int cc = (lane & 3) << 1;
#pragma unroll
    for (int j = 0; j < 8; j++) {
        *(float2*)(Pout + (size_t)r0 * DH_ + j * 8 + cc) =
            make_float2(acc[j][0], acc[j][1]);
        *(float2*)(Pout + (size_t)(r0 + 8) * DH_ + j * 8 + cc) =
            make_float2(acc[j][2], acc[j][3]);
    }
}

// ---------------------------------------------------------------------------
// Fused filter: H = sum_hop alpha[h,hop] * P[hop] @ W[h,hop]
// ---------------------------------------------------------------------------
__global__ __launch_bounds__(TPB, 2) void filter_kernel(const float* __restrict__ Wf,
                                                        const float* __restrict__ alpha) {
    __shared__ float4 As[2][64 * 16], Bs[2][64 * 16];
    int bh = blockIdx.y, b = bh >> 3, h = bh & 7;
    int mt = blockIdx.x << 6;
    int tx = threadIdx.x & 15, ty = threadIdx.x >> 4;

    float av[KHOP + 1];
#pragma unroll
    for (int k = 0; k <= KHOP; k++) av[k] = alpha[h * (KHOP + 1) + k];

    float4 ra[4], rb[4];
    ldg_tile(ra, &g_P[0][(size_t)bh * N_ * DH_ + (size_t)mt * DH_], DH_);
    ldg_tile(rb, Wf + (size_t)(h * (KHOP + 1)) * DH_ * DH_, DH_);
#pragma unroll
    for (int i = 0; i < 4; i++) {
        rb[i].x *= av[0]; rb[i].y *= av[0]; rb[i].z *= av[0]; rb[i].w *= av[0];
    }
    sts_tile(As[0], ra);
    sts_tile(Bs[0], rb);
    __syncthreads();

    u64 acc2[4][2];
#pragma unroll
    for (int i = 0; i < 4; i++) { acc2[i][0] = 0ull; acc2[i][1] = 0ull; }

#pragma unroll 1
    for (int hop = 0; hop <= KHOP; hop++) {
        int cur = hop & 1, nxt = cur ^ 1;
        if (hop < KHOP) {
            ldg_tile(ra, &g_P[hop + 1][(size_t)bh * N_ * DH_ + (size_t)mt * DH_], DH_);
            ldg_tile(rb, Wf + (size_t)(h * (KHOP + 1) + hop + 1) * DH_ * DH_, DH_);
            float a1 = av[hop + 1];
#pragma unroll
            for (int i = 0; i < 4; i++) {
                rb[i].x *= a1; rb[i].y *= a1; rb[i].z *= a1; rb[i].w *= a1;
            }
        }
        const float4* Ac = As[cur];
        const u64*   Bc2 = (const u64*)Bs[cur];
#pragma unroll
        for (int k4 = 0; k4 < 16; k4++) {
            float4 a[4];
#pragma unroll
            for (int i = 0; i < 4; i++) a[i] = Ac[(ty * 4 + i) * 16 + (k4 ^ ty)];
#pragma unroll
            for (int c = 0; c < 4; c++) {
                int f = ((k4 * 4 + c) * 16 + (tx ^ k4)) * 2;
                u64 bL = Bc2[f], bH = Bc2[f + 1];
#pragma unroll
                for (int i = 0; i < 4; i++) {
                    u64 s2 = dup2(getc(a[i], c));
                    acc2[i][0] = ffma2(s2, bL, acc2[i][0]);
                    acc2[i][1] = ffma2(s2, bH, acc2[i][1]);
                }
            }
        }
        if (hop < KHOP) {
            sts_tile(As[nxt], ra);
            sts_tile(Bs[nxt], rb);
        }
        __syncthreads();
    }

    float* Hb = g_H + ((size_t)(b * N_ + mt)) * D_ + h * DH_;
#pragma unroll
    for (int i = 0; i < 4; i++) {
        float2 p0 = unpack2(acc2[i][0]);
        float2 p1 = unpack2(acc2[i][1]);
        *(float4*)(Hb + (size_t)(ty * 4 + i) * D_ + tx * 4) =
            make_float4(p0.x, p0.y, p1.x, p1.y);
    }
}

// ---------------------------------------------------------------------------
// Projection: out = H @ W_proj^T + b_proj
// ---------------------------------------------------------------------------
__global__ __launch_bounds__(TPB) void proj_kernel(const float* __restrict__ Wp,
                                                   const float* __restrict__ bias,
                                                   float* __restrict__ out) {
    __shared__ float4 As[64 * 16], Bs[64 * 16];
    int it = blockIdx.y << 6;
    int jt = blockIdx.x << 6;
    int tx = threadIdx.x & 15, ty = threadIdx.x >> 4;
    const u64* As2 = (const u64*)As;
    const u64* Bs2 = (const u64*)Bs;

    u64 acc2[4][4];
#pragma unroll
    for (int i = 0; i < 4; i++)
#pragma unroll
        for (int j = 0; j < 4; j++) acc2[i][j] = 0ull;

    for (int kc = 0; kc < 8; kc++) {
        load_tile(As, g_H + (size_t)it * D_ + kc * 64, D_);
        load_tile(Bs, Wp + (size_t)jt * D_ + kc * 64, D_);
        __syncthreads();
#pragma unroll
        for (int k4 = 0; k4 < 16; k4++) {
            u64 aL[4], aH[4], bL[4], bH[4];
#pragma unroll
            for (int i = 0; i < 4; i++) {
                int f = ((ty * 4 + i) * 16 + (k4 ^ ty)) * 2;
                aL[i] = As2[f]; aH[i] = As2[f + 1];
            }
#pragma unroll
            for (int j = 0; j < 4; j++) {
                int f = ((tx * 4 + j) * 16 + (k4 ^ tx)) * 2;
                bL[j] = Bs2[f]; bH[j] = Bs2[f + 1];
            }
#pragma unroll
            for (int i = 0; i < 4; i++)
#pragma unroll
                for (int j = 0; j < 4; j++) {
                    acc2[i][j] = ffma2(aL[i], bL[j], acc2[i][j]);
                    acc2[i][j] = ffma2(aH[i], bH[j], acc2[i][j]);
                }
        }
        __syncthreads();
    }

    float4 bb4 = *(const float4*)(bias + jt + tx * 4);
#pragma unroll
    for (int i = 0; i < 4; i++) {
        float r[4];
#pragma unroll
        for (int j = 0; j < 4; j++) {
            float2 p = unpack2(acc2[i][j]);
            r[j] = p.x + p.y;
        }
        *(float4*)(out + (size_t)(it + ty * 4 + i) * D_ + jt + tx * 4) =
            make_float4(r[0] + bb4.x, r[1] + bb4.y, r[2] + bb4.z, r[3] + bb4.w);
    }
}

}  // namespace

extern "C" void kernel_launch(void* const* d_in, const int* in_sizes, int n_in,
                              void* d_out, int out_size) {
    const float* X           = (const float*)d_in[0];
    const float* temperature = (const float*)d_in[1];
    const float* W_filt      = (const float*)d_in[2];
    const float* alpha       = (const float*)d_in[3];
    const float* W_proj      = (const float*)d_in[4];
    const float* b_proj      = (const float*)d_in[5];
    const int*   layer_idx   = (const int*)d_in[6];
    const int*   Lp          = (const int*)d_in[7];
    float* out = (float*)d_out;
    (void)in_sizes; (void)n_in; (void)out_size;

    static bool attr_set = false;
    if (!attr_set) {
        cudaFuncSetAttribute(spmm_mma_kernel,
                             cudaFuncAttributeMaxDynamicSharedMemorySize, SMEM_SPMM);
        attr_set = true;
    }

    // 1) Pack Xh -> P[0]
    pack_kernel<<<2048, TPB>>>(X);
    // 2) Per-head scaled scores S (fp32)
    score_kernel<<<dim3(16, 16, 32), TPB>>>(X, temperature);
    // 3) Exact top-k + softmax -> adjacency as bf16 hi/lo
    topk_softmax_kernel<<<4096, TPB>>>(layer_idx, Lp);
    // 4) Hops 1..3 on tensor cores (mma.sync bf16x3)
    for (int k = 1; k <= KHOP; k++) {
        pt_convert_kernel<<<dim3(16, 32), 128>>>(k - 1);
        spmm_mma_kernel<<<dim3(16, 32), 128, SMEM_SPMM>>>(k);
    }
    // 5) Fused 4-hop filter -> H
    filter_kernel<<<dim3(16, 32), TPB>>>(W_filt, alpha);
    // 6) Output projection + bias
    proj_kernel<<<dim3(8, 64), TPB>>>(W_proj, b_proj, out);
}